// round 12
// baseline (speedup 1.0000x reference)
#include <cuda_runtime.h>
#include <cuda_bf16.h>
#include <cstdint>

#define ETH   256                        // edge kernel: 8 warps, m=32 per warp
#define NTH   512                        // node kernel: 16 warps, m=16 per warp
#define PTH   512
#define ST    136                        // bf16 per weight-tile row (272 B stride)
#define TILEB (128 * ST * 2)             // 34816 B per 128x128 bf16 tile
#define EDGE_SMEM (6 * TILEB)            // W1a'(h,l) W1b(h,l) W2(h,l) = 208896
#define NODE_SMEM (4 * TILEB)            // U(h,l) V(h,l) = 139264
#define NODE_PAD 100096

// ---------------- device scratch (static, allowed) ----------------
__device__ __align__(16) float gVU[(size_t)NODE_PAD * 128];
__device__ __align__(16) float gVV[(size_t)NODE_PAD * 128];
__device__ __align__(16) float gB1p[128];
__device__ __align__(16) char  gWimg[5][2][TILEB];  // 0:W1a' 1:W1b 2:W2 3:U_w 4:V_w

// ---------------- PTX helpers ----------------
__device__ __forceinline__ uint32_t smem_u32(const void* p) {
    uint32_t a;
    asm("{ .reg .u64 t; cvta.to.shared.u64 t, %1; cvt.u32.u64 %0, t; }" : "=r"(a) : "l"(p));
    return a;
}
#define LDSM4(r, addr)                                                              \
    asm volatile("ldmatrix.sync.aligned.m8n8.x4.shared.b16 {%0,%1,%2,%3}, [%4];"    \
                 : "=r"((r)[0]), "=r"((r)[1]), "=r"((r)[2]), "=r"((r)[3])           \
                 : "r"(addr))
__device__ __forceinline__ void mma_bf16(float* c, const uint32_t* a, uint32_t b0, uint32_t b1) {
    asm volatile("mma.sync.aligned.m16n8k16.row.col.f32.bf16.bf16.f32 "
                 "{%0,%1,%2,%3}, {%4,%5,%6,%7}, {%8,%9}, {%0,%1,%2,%3};"
                 : "+f"(c[0]), "+f"(c[1]), "+f"(c[2]), "+f"(c[3])
                 : "r"(a[0]), "r"(a[1]), "r"(a[2]), "r"(a[3]), "r"(b0), "r"(b1));
}
#define CP16(dst, src) \
    asm volatile("cp.async.ca.shared.global [%0], [%1], 16;" :: "r"(dst), "l"(src))
#define CP_COMMIT() asm volatile("cp.async.commit_group;" ::: "memory")
#define CP_WAIT()   asm volatile("cp.async.wait_group 0;" ::: "memory")

// ---------------- numeric helpers ----------------
__device__ __forceinline__ float bf16hi_rn(float a, uint32_t& hbits) {
    uint32_t u = __float_as_uint(a);
    uint32_t r = (u + 0x7FFFu + ((u >> 16) & 1u)) & 0xFFFF0000u;
    hbits = r;
    return __uint_as_float(r);
}
__device__ __forceinline__ uint32_t bf16x2_of(float lo, float hi) {
    uint32_t r;
    asm("cvt.rn.bf16x2.f32 %0, %1, %2;" : "=r"(r) : "f"(hi), "f"(lo));
    return r;
}
__device__ __forceinline__ void split2(float x, float y, uint32_t& h, uint32_t& l) {
    uint32_t rx, ry;
    float hx = bf16hi_rn(x, rx), hy = bf16hi_rn(y, ry);
    h = __byte_perm(rx, ry, 0x7632);
    l = bf16x2_of(x - hx, y - hy);
}
__device__ __forceinline__ float fast_tanh(float x) {
    float e = __expf(2.f * x);
    return 1.f - __fdividef(2.f, e + 1.f);
}
__device__ __forceinline__ float lk(float v) { return v > 0.f ? v : 0.01f * v; }

__device__ __forceinline__ void stage32(const float* __restrict__ src,
                                        char* Xh, char* Xl, uint32_t off) {
    #pragma unroll
    for (int i = 0; i < 8; ++i) {
        float4 t = reinterpret_cast<const float4*>(src)[i];
        uint32_t r0, r1, r2, r3;
        float h0 = bf16hi_rn(t.x, r0), h1 = bf16hi_rn(t.y, r1);
        float h2 = bf16hi_rn(t.z, r2), h3 = bf16hi_rn(t.w, r3);
        uint2 hh = make_uint2(__byte_perm(r0, r1, 0x7632), __byte_perm(r2, r3, 0x7632));
        uint2 ll = make_uint2(bf16x2_of(t.x - h0, t.y - h1), bf16x2_of(t.z - h2, t.w - h3));
        *reinterpret_cast<uint2*>(Xh + off + i * 8) = hh;
        *reinterpret_cast<uint2*>(Xl + off + i * 8) = ll;
    }
}

// ---------------- core MMA helpers ----------------
// single stream, one m16, one n16 group (node kernel)
__device__ __forceinline__ void mma6(float* acc, const uint32_t* ah, const uint32_t* al,
                                     const uint32_t* bh, const uint32_t* bl) {
    mma_bf16(acc,     ah, bh[0], bh[1]);
    mma_bf16(acc + 4, ah, bh[2], bh[3]);
    mma_bf16(acc,     ah, bl[0], bl[1]);
    mma_bf16(acc + 4, ah, bl[2], bl[3]);
    mma_bf16(acc,     al, bh[0], bh[1]);
    mma_bf16(acc + 4, al, bh[2], bh[3]);
}
// two streams x two m-blocks sharing one n16 B group: 24 MMAs, 4 quads rotated.
// Per-quad op order: tanh(h,bh)(h,bl)(l,bh) then E(h,bh)(h,bl)(l,bh) == R10 mma12.
__device__ __forceinline__ void mma24(float* a0, float* a1,
    const uint32_t* th0, const uint32_t* tl0, const uint32_t* th1, const uint32_t* tl1,
    const uint32_t* eh0, const uint32_t* el0, const uint32_t* eh1, const uint32_t* el1,
    const uint32_t* bha, const uint32_t* bla, const uint32_t* bhb, const uint32_t* blb)
{
    mma_bf16(a0,     th0, bha[0], bha[1]);
    mma_bf16(a0 + 4, th0, bha[2], bha[3]);
    mma_bf16(a1,     th1, bha[0], bha[1]);
    mma_bf16(a1 + 4, th1, bha[2], bha[3]);
    mma_bf16(a0,     th0, bla[0], bla[1]);
    mma_bf16(a0 + 4, th0, bla[2], bla[3]);
    mma_bf16(a1,     th1, bla[0], bla[1]);
    mma_bf16(a1 + 4, th1, bla[2], bla[3]);
    mma_bf16(a0,     tl0, bha[0], bha[1]);
    mma_bf16(a0 + 4, tl0, bha[2], bha[3]);
    mma_bf16(a1,     tl1, bha[0], bha[1]);
    mma_bf16(a1 + 4, tl1, bha[2], bha[3]);
    mma_bf16(a0,     eh0, bhb[0], bhb[1]);
    mma_bf16(a0 + 4, eh0, bhb[2], bhb[3]);
    mma_bf16(a1,     eh1, bhb[0], bhb[1]);
    mma_bf16(a1 + 4, eh1, bhb[2], bhb[3]);
    mma_bf16(a0,     eh0, blb[0], blb[1]);
    mma_bf16(a0 + 4, eh0, blb[2], blb[3]);
    mma_bf16(a1,     eh1, blb[0], blb[1]);
    mma_bf16(a1 + 4, eh1, blb[2], blb[3]);
    mma_bf16(a0,     el0, bhb[0], bhb[1]);
    mma_bf16(a0 + 4, el0, bhb[2], bhb[3]);
    mma_bf16(a1,     el1, bhb[0], bhb[1]);
    mma_bf16(a1 + 4, el1, bhb[2], bhb[3]);
}
// GEMM C: one y stream per m-block, two m-blocks sharing one n16 B group.
__device__ __forceinline__ void mma12c(float* a0, float* a1,
    const uint32_t* yh0, const uint32_t* yl0, const uint32_t* yh1, const uint32_t* yl1,
    const uint32_t* bh, const uint32_t* bl)
{
    mma_bf16(a0,     yh0, bh[0], bh[1]);
    mma_bf16(a0 + 4, yh0, bh[2], bh[3]);
    mma_bf16(a1,     yh1, bh[0], bh[1]);
    mma_bf16(a1 + 4, yh1, bh[2], bh[3]);
    mma_bf16(a0,     yh0, bl[0], bl[1]);
    mma_bf16(a0 + 4, yh0, bl[2], bl[3]);
    mma_bf16(a1,     yh1, bl[0], bl[1]);
    mma_bf16(a1 + 4, yh1, bl[2], bl[3]);
    mma_bf16(a0,     yl0, bh[0], bh[1]);
    mma_bf16(a0 + 4, yl0, bh[2], bh[3]);
    mma_bf16(a1,     yl1, bh[0], bh[1]);
    mma_bf16(a1 + 4, yl1, bh[2], bh[3]);
}
// n-group sweep with in-loop LDSM (node kernel)
__device__ __forceinline__ void gemm_groups(float* acc, const uint32_t* ah, const uint32_t* al,
                                            uint32_t baseH, uint32_t baseL, int ngroups)
{
    #pragma unroll
    for (int g = 0; g < 8; ++g) {
        if (g >= ngroups) break;
        uint32_t bh[4], bl[4];
        LDSM4(bh, baseH + g * (16 * ST * 2));
        LDSM4(bl, baseL + g * (16 * ST * 2));
        mma6(acc + 8 * g, ah, al, bh, bl);
    }
}

// ================= prep 1: W1a' = W1a @ P_w (emit bf16 image 0), b1' =================
__global__ void __launch_bounds__(128, 1)
ecat_compose(const float* __restrict__ W1, const float* __restrict__ P_w,
             const float* __restrict__ P_b, const float* __restrict__ b1)
{
    __shared__ float srow[128];
    int o = blockIdx.x;
    int j = threadIdx.x;
    srow[j] = W1[o * 256 + j];
    __syncthreads();
    float acc = 0.f;
    #pragma unroll 4
    for (int i = 0; i < 128; ++i)
        acc += srow[i] * P_w[i * 128 + j];
    uint32_t hb;
    float h = bf16hi_rn(acc, hb);
    uint32_t lo = bf16x2_of(acc - h, 0.f) & 0xFFFFu;
    reinterpret_cast<uint16_t*>(gWimg[0][0])[o * ST + j] = (uint16_t)(hb >> 16);
    reinterpret_cast<uint16_t*>(gWimg[0][1])[o * ST + j] = (uint16_t)lo;
    if (j == 0) {
        float s = 0.f;
        for (int i = 0; i < 128; ++i) s += srow[i] * P_b[i];
        gB1p[o] = b1[o] + s;
    }
}

// ================= prep 2: W1b, W2, U_w, V_w -> bf16 hi/lo smem images =================
__global__ void __launch_bounds__(PTH, 1)
ecat_convert(const float* __restrict__ W1, const float* __restrict__ W2,
             const float* __restrict__ U_w, const float* __restrict__ V_w)
{
    int b = blockIdx.x;
    int tid = threadIdx.x;
    int o = tid >> 2, qo = (tid & 3) * 32;
    const float* srcRow;
    if (b == 0)      srcRow = W1 + o * 256 + 128 + qo;          // W1b
    else if (b == 1) srcRow = W2 + o * 128 + qo;
    else if (b == 2) srcRow = U_w + (size_t)o * 128 + qo;
    else             srcRow = V_w + (size_t)o * 128 + qo;
    stage32(srcRow, (char*)gWimg[b + 1][0], (char*)gWimg[b + 1][1],
            (uint32_t)(o * ST + qo) * 2);
}

// ================= prep 3: VU = V@U_w^T, VV = V@V_w^T (persistent, m=16/warp) =================
__global__ void __launch_bounds__(NTH, 1)
ecat_node(const float* __restrict__ V, int n_nodes, int n_ntiles)
{
    extern __shared__ char sm[];
    uint32_t smb = smem_u32(sm);
    const char* gsrc = &gWimg[3][0][0];
    #pragma unroll
    for (int i = 0; i < 17; ++i) {
        int idx = i * NTH + threadIdx.x;
        CP16(smb + idx * 16, gsrc + idx * 16);   // 17*512 = 8704 chunks exactly
    }
    CP_COMMIT(); CP_WAIT();
    __syncthreads();

    const int tid = threadIdx.x, lane = tid & 31, w = tid >> 5;
    const int r0 = lane >> 2, il = lane & 3, cb = il * 2;
    const uint32_t offB = (uint32_t)(((lane & 7) + (((lane >> 4) & 1) << 3)) * ST
                                     + (((lane >> 3) & 1) << 3)) * 2;

    for (int t = blockIdx.x; t < n_ntiles; t += gridDim.x) {
        int n0 = t * 256 + w * 16 + r0;
        int n1 = n0 + 8;
        int n0c = n0 < n_nodes ? n0 : 0;
        int n1c = n1 < n_nodes ? n1 : 0;
        const float2* pa0 = reinterpret_cast<const float2*>(V + (size_t)n0c * 128);
        const float2* pa1 = reinterpret_cast<const float2*>(V + (size_t)n1c * 128);

        #pragma unroll 1
        for (int pass = 0; pass < 2; ++pass) {
            uint32_t bH = smb + pass * 2 * TILEB, bL = bH + TILEB;
            float acc[64];
            #pragma unroll
            for (int i = 0; i < 64; ++i) acc[i] = 0.f;
            #pragma unroll 1
            for (int ks = 0; ks < 8; ++ks) {
                int i0 = il + 8 * ks, i1 = i0 + 4;
                float2 a0 = pa0[i0], b0 = pa1[i0], c0 = pa0[i1], d0 = pa1[i1];
                uint32_t ah[4], al[4];
                split2(a0.x, a0.y, ah[0], al[0]);
                split2(b0.x, b0.y, ah[1], al[1]);
                split2(c0.x, c0.y, ah[2], al[2]);
                split2(d0.x, d0.y, ah[3], al[3]);
                gemm_groups(acc, ah, al, bH + offB + ks * 32, bL + offB + ks * 32, 8);
            }
            float* dstb = pass ? gVV : gVU;
            #pragma unroll
            for (int nf = 0; nf < 16; ++nf) {
                int c = nf * 8 + cb;
                if (n0 < n_nodes)
                    *reinterpret_cast<float2*>(dstb + (size_t)n0 * 128 + c) =
                        make_float2(acc[nf*4], acc[nf*4+1]);
                if (n1 < n_nodes)
                    *reinterpret_cast<float2*>(dstb + (size_t)n1 * 128 + c) =
                        make_float2(acc[nf*4+2], acc[nf*4+3]);
            }
        }
    }
}

// ================= main edge kernel: 8 warps, m=32/warp, shared-B everywhere =================
__global__ void __launch_bounds__(ETH, 1)
ecat_edge(const float* __restrict__ E, const int* __restrict__ src,
          const int* __restrict__ dst, const float* __restrict__ b2,
          float* __restrict__ out, int n_tiles)
{
    extern __shared__ char sm[];
    uint32_t smb = smem_u32(sm);
    const char* gsrc = &gWimg[0][0][0];
    #pragma unroll
    for (int i = 0; i < 51; ++i) {                 // 51*256 = 13056 = 6*TILEB/16 exactly
        int idx = i * ETH + threadIdx.x;
        CP16(smb + idx * 16, gsrc + idx * 16);
    }
    CP_COMMIT(); CP_WAIT();
    __syncthreads();

    const int tid = threadIdx.x, lane = tid & 31, w = tid >> 5;
    const int r0 = lane >> 2, il = lane & 3, cb = il * 2;
    const uint32_t offB = (uint32_t)(((lane & 7) + (((lane >> 4) & 1) << 3)) * ST
                                     + (((lane >> 3) & 1) << 3)) * 2;
    const uint32_t uW1aH = smb,             uW1aL = smb + TILEB;
    const uint32_t uW1bH = smb + 2 * TILEB, uW1bL = smb + 3 * TILEB;
    const uint32_t uW2H  = smb + 4 * TILEB, uW2L  = smb + 5 * TILEB;

    for (int t = blockIdx.x; t < n_tiles; t += gridDim.x) {
        long eb = (long)t * 256 + w * 32 + r0;     // warp rows: eb + 8q, q=0..3
        const float2* pu[4];
        const float2* pv[4];
        #pragma unroll
        for (int q = 0; q < 4; ++q) {
            long er = eb + q * 8;
            pu[q] = reinterpret_cast<const float2*>(gVU + (size_t)__ldg(src + er) * 128);
            pv[q] = reinterpret_cast<const float2*>(gVV + (size_t)__ldg(dst + er) * 128);
        }
        const float2* pe = reinterpret_cast<const float2*>(E + eb * 128);  // row q at +512q

        float acc0[64], acc1[64];                  // m-block 0: rows q0,q1; 1: q2,q3
        #pragma unroll
        for (int i = 0; i < 64; ++i) { acc0[i] = 0.f; acc1[i] = 0.f; }

        // ---- merged GEMM A+B: both m-blocks and both streams share every B group ----
        #pragma unroll 1
        for (int ks = 0; ks < 8; ++ks) {
            int i0 = il + 8 * ks, i1 = i0 + 4;
            uint32_t th0[4], tl0[4], th1[4], tl1[4];
            uint32_t eh0[4], el0[4], eh1[4], el1[4];
            {
                float2 u0 = pu[0][i0], u1 = pu[1][i0], u2 = pu[0][i1], u3 = pu[1][i1];
                float2 v0 = pv[0][i0], v1 = pv[1][i0], v2 = pv[0][i1], v3 = pv[1][i1];
                split2(fast_tanh(u0.x * v0.x), fast_tanh(u0.y * v0.y), th0[0], tl0[0]);
                split2(fast_tanh(u1.x * v1.x), fast_tanh(u1.y * v1.y), th0[1], tl0[1]);
                split2(fast_tanh(u2.x * v2.x), fast_tanh(u2.y * v2.y), th0[2], tl0[2]);
                split2(fast_tanh(u3.x * v3.x), fast_tanh(u3.y * v3.y), th0[3], tl0[3]);
            }
            {
                float2 u0 = pu[2][i0], u1 = pu[3][i0], u2 = pu[2][i1], u3 = pu[3][i1];
                float2 v0 = pv[2][i0], v1 = pv[3][i0], v2 = pv[2][i1], v3 = pv[3][i1];
                split2(fast_tanh(u0.x * v0.x), fast_tanh(u0.y * v0.y), th1[0], tl1[0]);
                split2(fast_tanh(u1.x * v1.x), fast_tanh(u1.y * v1.y), th1[1], tl1[1]);
                split2(fast_tanh(u2.x * v2.x), fast_tanh(u2.y * v2.y), th1[2], tl1[2]);
                split2(fast_tanh(u3.x * v3.x), fast_tanh(u3.y * v3.y), th1[3], tl1[3]);
            }
            {
                float2 e0 = pe[i0],        e1 = pe[512 + i0];
                float2 e2 = pe[i1],        e3 = pe[512 + i1];
                split2(lk(e0.x), lk(e0.y), eh0[0], el0[0]);
                split2(lk(e1.x), lk(e1.y), eh0[1], el0[1]);
                split2(lk(e2.x), lk(e2.y), eh0[2], el0[2]);
                split2(lk(e3.x), lk(e3.y), eh0[3], el0[3]);
                float2 f0 = pe[1024 + i0], f1 = pe[1536 + i0];
                float2 f2 = pe[1024 + i1], f3 = pe[1536 + i1];
                split2(lk(f0.x), lk(f0.y), eh1[0], el1[0]);
                split2(lk(f1.x), lk(f1.y), eh1[1], el1[1]);
                split2(lk(f2.x), lk(f2.y), eh1[2], el1[2]);
                split2(lk(f3.x), lk(f3.y), eh1[3], el1[3]);
            }
            const uint32_t bAH = uW1aH + offB + ks * 32, bAL = uW1aL + offB + ks * 32;
            const uint32_t bBH = uW1bH + offB + ks * 32, bBL = uW1bL + offB + ks * 32;
            #pragma unroll
            for (int g = 0; g < 8; ++g) {
                uint32_t go = (uint32_t)g * (16 * ST * 2);
                uint32_t bha[4], bla[4], bhb[4], blb[4];
                LDSM4(bha, bAH + go);
                LDSM4(bhb, bBH + go);
                LDSM4(bla, bAL + go);
                LDSM4(blb, bBL + go);
                mma24(acc0 + 8 * g, acc1 + 8 * g,
                      th0, tl0, th1, tl1, eh0, el0, eh1, el1,
                      bha, bla, bhb, blb);
            }
        }

        // ---- y1 = relu(acc + b1'): repack both m-blocks into GEMM-C A-frags ----
        uint32_t yh0[8][4], yl0[8][4], yh1[8][4], yl1[8][4];
        #pragma unroll
        for (int ks = 0; ks < 8; ++ks) {
            #pragma unroll
            for (int p = 0; p < 2; ++p) {
                int nf = 2 * ks + p;
                float2 bb = __ldg(reinterpret_cast<const float2*>(gB1p + nf * 8 + cb));
                split2(fmaxf(acc0[nf*4+0] + bb.x, 0.f), fmaxf(acc0[nf*4+1] + bb.y, 0.f),
                       yh0[ks][2*p], yl0[ks][2*p]);
                split2(fmaxf(acc0[nf*4+2] + bb.x, 0.f), fmaxf(acc0[nf*4+3] + bb.y, 0.f),
                       yh0[ks][2*p+1], yl0[ks][2*p+1]);
                split2(fmaxf(acc1[nf*4+0] + bb.x, 0.f), fmaxf(acc1[nf*4+1] + bb.y, 0.f),
                       yh1[ks][2*p], yl1[ks][2*p]);
                split2(fmaxf(acc1[nf*4+2] + bb.x, 0.f), fmaxf(acc1[nf*4+3] + bb.y, 0.f),
                       yh1[ks][2*p+1], yl1[ks][2*p+1]);
            }
        }

        // ---- GEMM C: n in halves; both m-blocks share each B group ----
        #pragma unroll 1
        for (int h = 0; h < 2; ++h) {
            float c0[32], c1[32];
            #pragma unroll
            for (int i = 0; i < 32; ++i) { c0[i] = 0.f; c1[i] = 0.f; }
            uint32_t hb = (uint32_t)h * (64 * ST * 2);
            #pragma unroll 1
            for (int ks = 0; ks < 8; ++ks) {
                const uint32_t bHk = uW2H + offB + hb + ks * 32;
                const uint32_t bLk = uW2L + offB + hb + ks * 32;
                #pragma unroll
                for (int g = 0; g < 4; ++g) {
                    uint32_t go = (uint32_t)g * (16 * ST * 2);
                    uint32_t bh[4], bl[4];
                    LDSM4(bh, bHk + go);
                    LDSM4(bl, bLk + go);
                    mma12c(c0 + 8 * g, c1 + 8 * g,
                           yh0[ks], yl0[ks], yh1[ks], yl1[ks], bh, bl);
                }
            }
            #pragma unroll
            for (int nf = 0; nf < 8; ++nf) {
                int c = h * 64 + nf * 8 + cb;
                float2 bb = __ldg(reinterpret_cast<const float2*>(b2 + c));
                *reinterpret_cast<float2*>(out + (eb)      * 128 + c) =
                    make_float2(fmaxf(c0[nf*4+0] + bb.x, 0.f), fmaxf(c0[nf*4+1] + bb.y, 0.f));
                *reinterpret_cast<float2*>(out + (eb + 8)  * 128 + c) =
                    make_float2(fmaxf(c0[nf*4+2] + bb.x, 0.f), fmaxf(c0[nf*4+3] + bb.y, 0.f));
                *reinterpret_cast<float2*>(out + (eb + 16) * 128 + c) =
                    make_float2(fmaxf(c1[nf*4+0] + bb.x, 0.f), fmaxf(c1[nf*4+1] + bb.y, 0.f));
                *reinterpret_cast<float2*>(out + (eb + 24) * 128 + c) =
                    make_float2(fmaxf(c1[nf*4+2] + bb.x, 0.f), fmaxf(c1[nf*4+3] + bb.y, 0.f));
            }
        }
    }
}

// ================= host =================
extern "C" void kernel_launch(void* const* d_in, const int* in_sizes, int n_in,
                              void* d_out, int out_size)
{
    const float* V   = (const float*)d_in[0];
    const float* E   = (const float*)d_in[1];
    const int*   src = (const int*)d_in[2];
    const int*   dst = (const int*)d_in[3];
    const float* U_w = (const float*)d_in[4];
    const float* V_w = (const float*)d_in[5];
    const float* P_w = (const float*)d_in[6];
    const float* P_b = (const float*)d_in[7];
    const float* W1  = (const float*)d_in[8];
    const float* b1  = (const float*)d_in[9];
    const float* W2  = (const float*)d_in[10];
    const float* b2  = (const float*)d_in[11];
    float* out = (float*)d_out;

    int n_nodes = in_sizes[0] / 128;
    int n_edges = in_sizes[2];
    int n_tiles = n_edges / 256;                 // 2500
    int n_ntiles = (n_nodes + 255) / 256;        // 391

    static int sms = 0;
    if (!sms) {
        cudaDeviceGetAttribute(&sms, cudaDevAttrMultiProcessorCount, 0);
        cudaFuncSetAttribute(ecat_node, cudaFuncAttributeMaxDynamicSharedMemorySize, NODE_SMEM);
        cudaFuncSetAttribute(ecat_edge, cudaFuncAttributeMaxDynamicSharedMemorySize, EDGE_SMEM);
    }

    ecat_compose<<<128, 128>>>(W1, P_w, P_b, b1);
    ecat_convert<<<4, PTH>>>(W1, W2, U_w, V_w);
    ecat_node<<<sms, NTH, NODE_SMEM>>>(V, n_nodes, n_ntiles);
    ecat_edge<<<sms, ETH, EDGE_SMEM>>>(E, src, dst, b2, out, n_tiles);
}

// round 13
// speedup vs baseline: 1.1686x; 1.1686x over previous
#include <cuda_runtime.h>
#include <cuda_bf16.h>
#include <cstdint>

#define ETH   256                        // edge kernel: 8 warps, m=32 per warp
#define NTH   512                        // node kernel: 16 warps, m=16 per warp
#define PTH   512
#define ST    136                        // bf16 per weight-tile row (272 B stride)
#define TILEB (128 * ST * 2)             // 34816 B per 128x128 bf16 tile
#define EDGE_SMEM (6 * TILEB)            // W1a'(h,l) W1b(h,l) W2(h,l) = 208896
#define NODE_SMEM (4 * TILEB)            // U(h,l) V(h,l) = 139264
#define NODE_PAD 100096

// ---------------- device scratch (static, allowed) ----------------
__device__ __align__(16) float gVU[(size_t)NODE_PAD * 128];
__device__ __align__(16) float gVV[(size_t)NODE_PAD * 128];
__device__ __align__(16) float gB1p[128];
__device__ __align__(16) char  gWimg[5][2][TILEB];  // 0:W1a' 1:W1b 2:W2 3:U_w 4:V_w

// ---------------- PTX helpers ----------------
__device__ __forceinline__ uint32_t smem_u32(const void* p) {
    uint32_t a;
    asm("{ .reg .u64 t; cvta.to.shared.u64 t, %1; cvt.u32.u64 %0, t; }" : "=r"(a) : "l"(p));
    return a;
}
#define LDSM4(r, addr)                                                              \
    asm volatile("ldmatrix.sync.aligned.m8n8.x4.shared.b16 {%0,%1,%2,%3}, [%4];"    \
                 : "=r"((r)[0]), "=r"((r)[1]), "=r"((r)[2]), "=r"((r)[3])           \
                 : "r"(addr))
__device__ __forceinline__ void mma_bf16(float* c, const uint32_t* a, uint32_t b0, uint32_t b1) {
    asm volatile("mma.sync.aligned.m16n8k16.row.col.f32.bf16.bf16.f32 "
                 "{%0,%1,%2,%3}, {%4,%5,%6,%7}, {%8,%9}, {%0,%1,%2,%3};"
                 : "+f"(c[0]), "+f"(c[1]), "+f"(c[2]), "+f"(c[3])
                 : "r"(a[0]), "r"(a[1]), "r"(a[2]), "r"(a[3]), "r"(b0), "r"(b1));
}
#define CP16(dst, src) \
    asm volatile("cp.async.ca.shared.global [%0], [%1], 16;" :: "r"(dst), "l"(src))
#define CP_COMMIT() asm volatile("cp.async.commit_group;" ::: "memory")
#define CP_WAIT()   asm volatile("cp.async.wait_group 0;" ::: "memory")

// ---------------- numeric helpers ----------------
__device__ __forceinline__ float bf16hi_rn(float a, uint32_t& hbits) {
    uint32_t u = __float_as_uint(a);
    uint32_t r = (u + 0x7FFFu + ((u >> 16) & 1u)) & 0xFFFF0000u;
    hbits = r;
    return __uint_as_float(r);
}
__device__ __forceinline__ uint32_t bf16x2_of(float lo, float hi) {
    uint32_t r;
    asm("cvt.rn.bf16x2.f32 %0, %1, %2;" : "=r"(r) : "f"(hi), "f"(lo));
    return r;
}
__device__ __forceinline__ void split2(float x, float y, uint32_t& h, uint32_t& l) {
    uint32_t rx, ry;
    float hx = bf16hi_rn(x, rx), hy = bf16hi_rn(y, ry);
    h = __byte_perm(rx, ry, 0x7632);
    l = bf16x2_of(x - hx, y - hy);
}
__device__ __forceinline__ float fast_tanh(float x) {
    float e = __expf(2.f * x);
    return 1.f - __fdividef(2.f, e + 1.f);
}
__device__ __forceinline__ float lk(float v) { return v > 0.f ? v : 0.01f * v; }

__device__ __forceinline__ void stage32(const float* __restrict__ src,
                                        char* Xh, char* Xl, uint32_t off) {
    #pragma unroll
    for (int i = 0; i < 8; ++i) {
        float4 t = reinterpret_cast<const float4*>(src)[i];
        uint32_t r0, r1, r2, r3;
        float h0 = bf16hi_rn(t.x, r0), h1 = bf16hi_rn(t.y, r1);
        float h2 = bf16hi_rn(t.z, r2), h3 = bf16hi_rn(t.w, r3);
        uint2 hh = make_uint2(__byte_perm(r0, r1, 0x7632), __byte_perm(r2, r3, 0x7632));
        uint2 ll = make_uint2(bf16x2_of(t.x - h0, t.y - h1), bf16x2_of(t.z - h2, t.w - h3));
        *reinterpret_cast<uint2*>(Xh + off + i * 8) = hh;
        *reinterpret_cast<uint2*>(Xl + off + i * 8) = ll;
    }
}

// ---------------- core MMA helpers ----------------
// single stream, one m16, one n16 group (node kernel)
__device__ __forceinline__ void mma6(float* acc, const uint32_t* ah, const uint32_t* al,
                                     const uint32_t* bh, const uint32_t* bl) {
    mma_bf16(acc,     ah, bh[0], bh[1]);
    mma_bf16(acc + 4, ah, bh[2], bh[3]);
    mma_bf16(acc,     ah, bl[0], bl[1]);
    mma_bf16(acc + 4, ah, bl[2], bl[3]);
    mma_bf16(acc,     al, bh[0], bh[1]);
    mma_bf16(acc + 4, al, bh[2], bh[3]);
}
// two streams x two m-blocks sharing one n16 B group: 24 MMAs.
// Per-quad op order identical to R10 mma12 (tanh h/bh, h/bl, l/bh; then E ...).
__device__ __forceinline__ void mma24(float* a0, float* a1,
    const uint32_t* th0, const uint32_t* tl0, const uint32_t* th1, const uint32_t* tl1,
    const uint32_t* eh0, const uint32_t* el0, const uint32_t* eh1, const uint32_t* el1,
    const uint32_t* bha, const uint32_t* bla, const uint32_t* bhb, const uint32_t* blb)
{
    mma_bf16(a0,     th0, bha[0], bha[1]);
    mma_bf16(a0 + 4, th0, bha[2], bha[3]);
    mma_bf16(a1,     th1, bha[0], bha[1]);
    mma_bf16(a1 + 4, th1, bha[2], bha[3]);
    mma_bf16(a0,     th0, bla[0], bla[1]);
    mma_bf16(a0 + 4, th0, bla[2], bla[3]);
    mma_bf16(a1,     th1, bla[0], bla[1]);
    mma_bf16(a1 + 4, th1, bla[2], bla[3]);
    mma_bf16(a0,     tl0, bha[0], bha[1]);
    mma_bf16(a0 + 4, tl0, bha[2], bha[3]);
    mma_bf16(a1,     tl1, bha[0], bha[1]);
    mma_bf16(a1 + 4, tl1, bha[2], bha[3]);
    mma_bf16(a0,     eh0, bhb[0], bhb[1]);
    mma_bf16(a0 + 4, eh0, bhb[2], bhb[3]);
    mma_bf16(a1,     eh1, bhb[0], bhb[1]);
    mma_bf16(a1 + 4, eh1, bhb[2], bhb[3]);
    mma_bf16(a0,     eh0, blb[0], blb[1]);
    mma_bf16(a0 + 4, eh0, blb[2], blb[3]);
    mma_bf16(a1,     eh1, blb[0], blb[1]);
    mma_bf16(a1 + 4, eh1, blb[2], blb[3]);
    mma_bf16(a0,     el0, bhb[0], bhb[1]);
    mma_bf16(a0 + 4, el0, bhb[2], bhb[3]);
    mma_bf16(a1,     el1, bhb[0], bhb[1]);
    mma_bf16(a1 + 4, el1, bhb[2], bhb[3]);
}
// GEMM C: one y stream per m-block, two m-blocks sharing one n16 B group.
__device__ __forceinline__ void mma12c(float* a0, float* a1,
    const uint32_t* yh0, const uint32_t* yl0, const uint32_t* yh1, const uint32_t* yl1,
    const uint32_t* bh, const uint32_t* bl)
{
    mma_bf16(a0,     yh0, bh[0], bh[1]);
    mma_bf16(a0 + 4, yh0, bh[2], bh[3]);
    mma_bf16(a1,     yh1, bh[0], bh[1]);
    mma_bf16(a1 + 4, yh1, bh[2], bh[3]);
    mma_bf16(a0,     yh0, bl[0], bl[1]);
    mma_bf16(a0 + 4, yh0, bl[2], bl[3]);
    mma_bf16(a1,     yh1, bl[0], bl[1]);
    mma_bf16(a1 + 4, yh1, bl[2], bl[3]);
    mma_bf16(a0,     yl0, bh[0], bh[1]);
    mma_bf16(a0 + 4, yl0, bh[2], bh[3]);
    mma_bf16(a1,     yl1, bh[0], bh[1]);
    mma_bf16(a1 + 4, yl1, bh[2], bh[3]);
}
// n-group sweep with in-loop LDSM (node kernel)
__device__ __forceinline__ void gemm_groups(float* acc, const uint32_t* ah, const uint32_t* al,
                                            uint32_t baseH, uint32_t baseL, int ngroups)
{
    #pragma unroll
    for (int g = 0; g < 8; ++g) {
        if (g >= ngroups) break;
        uint32_t bh[4], bl[4];
        LDSM4(bh, baseH + g * (16 * ST * 2));
        LDSM4(bl, baseL + g * (16 * ST * 2));
        mma6(acc + 8 * g, ah, al, bh, bl);
    }
}

// ================= prep 1: W1a' = W1a @ P_w (emit bf16 image 0), b1' =================
__global__ void __launch_bounds__(128, 1)
ecat_compose(const float* __restrict__ W1, const float* __restrict__ P_w,
             const float* __restrict__ P_b, const float* __restrict__ b1)
{
    __shared__ float srow[128];
    int o = blockIdx.x;
    int j = threadIdx.x;
    srow[j] = W1[o * 256 + j];
    __syncthreads();
    float acc = 0.f;
    #pragma unroll 4
    for (int i = 0; i < 128; ++i)
        acc += srow[i] * P_w[i * 128 + j];
    uint32_t hb;
    float h = bf16hi_rn(acc, hb);
    uint32_t lo = bf16x2_of(acc - h, 0.f) & 0xFFFFu;
    reinterpret_cast<uint16_t*>(gWimg[0][0])[o * ST + j] = (uint16_t)(hb >> 16);
    reinterpret_cast<uint16_t*>(gWimg[0][1])[o * ST + j] = (uint16_t)lo;
    if (j == 0) {
        float s = 0.f;
        for (int i = 0; i < 128; ++i) s += srow[i] * P_b[i];
        gB1p[o] = b1[o] + s;
    }
}

// ================= prep 2: W1b, W2, U_w, V_w -> bf16 hi/lo smem images =================
__global__ void __launch_bounds__(PTH, 1)
ecat_convert(const float* __restrict__ W1, const float* __restrict__ W2,
             const float* __restrict__ U_w, const float* __restrict__ V_w)
{
    int b = blockIdx.x;
    int tid = threadIdx.x;
    int o = tid >> 2, qo = (tid & 3) * 32;
    const float* srcRow;
    if (b == 0)      srcRow = W1 + o * 256 + 128 + qo;          // W1b
    else if (b == 1) srcRow = W2 + o * 128 + qo;
    else if (b == 2) srcRow = U_w + (size_t)o * 128 + qo;
    else             srcRow = V_w + (size_t)o * 128 + qo;
    stage32(srcRow, (char*)gWimg[b + 1][0], (char*)gWimg[b + 1][1],
            (uint32_t)(o * ST + qo) * 2);
}

// ================= prep 3: VU = V@U_w^T, VV = V@V_w^T (persistent, m=16/warp) =================
__global__ void __launch_bounds__(NTH, 1)
ecat_node(const float* __restrict__ V, int n_nodes, int n_ntiles)
{
    extern __shared__ char sm[];
    uint32_t smb = smem_u32(sm);
    const char* gsrc = &gWimg[3][0][0];
    #pragma unroll
    for (int i = 0; i < 17; ++i) {
        int idx = i * NTH + threadIdx.x;
        CP16(smb + idx * 16, gsrc + idx * 16);   // 17*512 = 8704 chunks exactly
    }
    CP_COMMIT(); CP_WAIT();
    __syncthreads();

    const int tid = threadIdx.x, lane = tid & 31, w = tid >> 5;
    const int r0 = lane >> 2, il = lane & 3, cb = il * 2;
    const uint32_t offB = (uint32_t)(((lane & 7) + (((lane >> 4) & 1) << 3)) * ST
                                     + (((lane >> 3) & 1) << 3)) * 2;

    for (int t = blockIdx.x; t < n_ntiles; t += gridDim.x) {
        int n0 = t * 256 + w * 16 + r0;
        int n1 = n0 + 8;
        int n0c = n0 < n_nodes ? n0 : 0;
        int n1c = n1 < n_nodes ? n1 : 0;
        const float2* pa0 = reinterpret_cast<const float2*>(V + (size_t)n0c * 128);
        const float2* pa1 = reinterpret_cast<const float2*>(V + (size_t)n1c * 128);

        #pragma unroll 1
        for (int pass = 0; pass < 2; ++pass) {
            uint32_t bH = smb + pass * 2 * TILEB, bL = bH + TILEB;
            float acc[64];
            #pragma unroll
            for (int i = 0; i < 64; ++i) acc[i] = 0.f;
            #pragma unroll 1
            for (int ks = 0; ks < 8; ++ks) {
                int i0 = il + 8 * ks, i1 = i0 + 4;
                float2 a0 = pa0[i0], b0 = pa1[i0], c0 = pa0[i1], d0 = pa1[i1];
                uint32_t ah[4], al[4];
                split2(a0.x, a0.y, ah[0], al[0]);
                split2(b0.x, b0.y, ah[1], al[1]);
                split2(c0.x, c0.y, ah[2], al[2]);
                split2(d0.x, d0.y, ah[3], al[3]);
                gemm_groups(acc, ah, al, bH + offB + ks * 32, bL + offB + ks * 32, 8);
            }
            float* dstb = pass ? gVV : gVU;
            #pragma unroll
            for (int nf = 0; nf < 16; ++nf) {
                int c = nf * 8 + cb;
                if (n0 < n_nodes)
                    *reinterpret_cast<float2*>(dstb + (size_t)n0 * 128 + c) =
                        make_float2(acc[nf*4], acc[nf*4+1]);
                if (n1 < n_nodes)
                    *reinterpret_cast<float2*>(dstb + (size_t)n1 * 128 + c) =
                        make_float2(acc[nf*4+2], acc[nf*4+3]);
            }
        }
    }
}

// ================= main edge kernel: 8 warps, m=32/warp, n-halved GEMM-1 passes =================
__global__ void __launch_bounds__(ETH, 1)
ecat_edge(const float* __restrict__ E, const int* __restrict__ src,
          const int* __restrict__ dst, const float* __restrict__ b2,
          float* __restrict__ out, int n_tiles)
{
    extern __shared__ char sm[];
    uint32_t smb = smem_u32(sm);
    const char* gsrc = &gWimg[0][0][0];
    #pragma unroll
    for (int i = 0; i < 51; ++i) {                 // 51*256 = 13056 = 6*TILEB/16 exactly
        int idx = i * ETH + threadIdx.x;
        CP16(smb + idx * 16, gsrc + idx * 16);
    }
    CP_COMMIT(); CP_WAIT();
    __syncthreads();

    const int tid = threadIdx.x, lane = tid & 31, w = tid >> 5;
    const int r0 = lane >> 2, il = lane & 3, cb = il * 2;
    const uint32_t offB = (uint32_t)(((lane & 7) + (((lane >> 4) & 1) << 3)) * ST
                                     + (((lane >> 3) & 1) << 3)) * 2;
    const uint32_t uW1aH = smb,             uW1aL = smb + TILEB;
    const uint32_t uW1bH = smb + 2 * TILEB, uW1bL = smb + 3 * TILEB;
    const uint32_t uW2H  = smb + 4 * TILEB, uW2L  = smb + 5 * TILEB;

    for (int t = blockIdx.x; t < n_tiles; t += gridDim.x) {
        long eb = (long)t * 256 + w * 32 + r0;     // warp rows: eb + 8q, q=0..3
        const float2* pu[4];
        const float2* pv[4];
        #pragma unroll
        for (int q = 0; q < 4; ++q) {
            long er = eb + q * 8;
            pu[q] = reinterpret_cast<const float2*>(gVU + (size_t)__ldg(src + er) * 128);
            pv[q] = reinterpret_cast<const float2*>(gVV + (size_t)__ldg(dst + er) * 128);
        }
        const float2* pe = reinterpret_cast<const float2*>(E + eb * 128);  // row q at +512q

        uint32_t yh0[8][4], yl0[8][4], yh1[8][4], yl1[8][4];   // filled half by half

        // ---- GEMM A+B in two n=64 halves; acc dies into y-frags per half ----
        #pragma unroll 1
        for (int h = 0; h < 2; ++h) {
            float acc0[32], acc1[32];
            #pragma unroll
            for (int i = 0; i < 32; ++i) { acc0[i] = 0.f; acc1[i] = 0.f; }
            const uint32_t hoff = (uint32_t)h * (64 * ST * 2);

            #pragma unroll 1
            for (int ks = 0; ks < 8; ++ks) {
                int i0 = il + 8 * ks, i1 = i0 + 4;
                uint32_t th0[4], tl0[4], th1[4], tl1[4];
                uint32_t eh0[4], el0[4], eh1[4], el1[4];
                {
                    float2 u0 = pu[0][i0], u1 = pu[1][i0], u2 = pu[0][i1], u3 = pu[1][i1];
                    float2 v0 = pv[0][i0], v1 = pv[1][i0], v2 = pv[0][i1], v3 = pv[1][i1];
                    split2(fast_tanh(u0.x * v0.x), fast_tanh(u0.y * v0.y), th0[0], tl0[0]);
                    split2(fast_tanh(u1.x * v1.x), fast_tanh(u1.y * v1.y), th0[1], tl0[1]);
                    split2(fast_tanh(u2.x * v2.x), fast_tanh(u2.y * v2.y), th0[2], tl0[2]);
                    split2(fast_tanh(u3.x * v3.x), fast_tanh(u3.y * v3.y), th0[3], tl0[3]);
                }
                {
                    float2 u0 = pu[2][i0], u1 = pu[3][i0], u2 = pu[2][i1], u3 = pu[3][i1];
                    float2 v0 = pv[2][i0], v1 = pv[3][i0], v2 = pv[2][i1], v3 = pv[3][i1];
                    split2(fast_tanh(u0.x * v0.x), fast_tanh(u0.y * v0.y), th1[0], tl1[0]);
                    split2(fast_tanh(u1.x * v1.x), fast_tanh(u1.y * v1.y), th1[1], tl1[1]);
                    split2(fast_tanh(u2.x * v2.x), fast_tanh(u2.y * v2.y), th1[2], tl1[2]);
                    split2(fast_tanh(u3.x * v3.x), fast_tanh(u3.y * v3.y), th1[3], tl1[3]);
                }
                {
                    float2 e0 = pe[i0],        e1 = pe[512 + i0];
                    float2 e2 = pe[i1],        e3 = pe[512 + i1];
                    split2(lk(e0.x), lk(e0.y), eh0[0], el0[0]);
                    split2(lk(e1.x), lk(e1.y), eh0[1], el0[1]);
                    split2(lk(e2.x), lk(e2.y), eh0[2], el0[2]);
                    split2(lk(e3.x), lk(e3.y), eh0[3], el0[3]);
                    float2 f0 = pe[1024 + i0], f1 = pe[1536 + i0];
                    float2 f2 = pe[1024 + i1], f3 = pe[1536 + i1];
                    split2(lk(f0.x), lk(f0.y), eh1[0], el1[0]);
                    split2(lk(f1.x), lk(f1.y), eh1[1], el1[1]);
                    split2(lk(f2.x), lk(f2.y), eh1[2], el1[2]);
                    split2(lk(f3.x), lk(f3.y), eh1[3], el1[3]);
                }
                const uint32_t bAH = uW1aH + offB + hoff + ks * 32;
                const uint32_t bAL = uW1aL + offB + hoff + ks * 32;
                const uint32_t bBH = uW1bH + offB + hoff + ks * 32;
                const uint32_t bBL = uW1bL + offB + hoff + ks * 32;
                #pragma unroll
                for (int g = 0; g < 4; ++g) {
                    uint32_t go = (uint32_t)g * (16 * ST * 2);
                    uint32_t bha[4], bla[4], bhb[4], blb[4];
                    LDSM4(bha, bAH + go);
                    LDSM4(bhb, bBH + go);
                    LDSM4(bla, bAL + go);
                    LDSM4(blb, bBL + go);
                    mma24(acc0 + 8 * g, acc1 + 8 * g,
                          th0, tl0, th1, tl1, eh0, el0, eh1, el1,
                          bha, bla, bhb, blb);
                }
            }

            // ---- repack this half: y1 = relu(acc + b1'); acc dead after this ----
            #pragma unroll
            for (int kl = 0; kl < 4; ++kl) {
                #pragma unroll
                for (int p = 0; p < 2; ++p) {
                    int nf = 2 * kl + p;
                    int ksC = 4 * h + kl;
                    float2 bb = __ldg(reinterpret_cast<const float2*>(
                                          gB1p + h * 64 + nf * 8 + cb));
                    split2(fmaxf(acc0[nf*4+0] + bb.x, 0.f), fmaxf(acc0[nf*4+1] + bb.y, 0.f),
                           yh0[ksC][2*p], yl0[ksC][2*p]);
                    split2(fmaxf(acc0[nf*4+2] + bb.x, 0.f), fmaxf(acc0[nf*4+3] + bb.y, 0.f),
                           yh0[ksC][2*p+1], yl0[ksC][2*p+1]);
                    split2(fmaxf(acc1[nf*4+0] + bb.x, 0.f), fmaxf(acc1[nf*4+1] + bb.y, 0.f),
                           yh1[ksC][2*p], yl1[ksC][2*p]);
                    split2(fmaxf(acc1[nf*4+2] + bb.x, 0.f), fmaxf(acc1[nf*4+3] + bb.y, 0.f),
                           yh1[ksC][2*p+1], yl1[ksC][2*p+1]);
                }
            }
        }

        // ---- GEMM C: n in halves; both m-blocks share each B group ----
        #pragma unroll 1
        for (int h = 0; h < 2; ++h) {
            float c0[32], c1[32];
            #pragma unroll
            for (int i = 0; i < 32; ++i) { c0[i] = 0.f; c1[i] = 0.f; }
            uint32_t hb = (uint32_t)h * (64 * ST * 2);
            #pragma unroll 1
            for (int ks = 0; ks < 8; ++ks) {
                const uint32_t bHk = uW2H + offB + hb + ks * 32;
                const uint32_t bLk = uW2L + offB + hb + ks * 32;
                #pragma unroll
                for (int g = 0; g < 4; ++g) {
                    uint32_t go = (uint32_t)g * (16 * ST * 2);
                    uint32_t bh[4], bl[4];
                    LDSM4(bh, bHk + go);
                    LDSM4(bl, bLk + go);
                    mma12c(c0 + 8 * g, c1 + 8 * g,
                           yh0[ks], yl0[ks], yh1[ks], yl1[ks], bh, bl);
                }
            }
            #pragma unroll
            for (int nf = 0; nf < 8; ++nf) {
                int c = h * 64 + nf * 8 + cb;
                float2 bb = __ldg(reinterpret_cast<const float2*>(b2 + c));
                *reinterpret_cast<float2*>(out + (eb)      * 128 + c) =
                    make_float2(fmaxf(c0[nf*4+0] + bb.x, 0.f), fmaxf(c0[nf*4+1] + bb.y, 0.f));
                *reinterpret_cast<float2*>(out + (eb + 8)  * 128 + c) =
                    make_float2(fmaxf(c0[nf*4+2] + bb.x, 0.f), fmaxf(c0[nf*4+3] + bb.y, 0.f));
                *reinterpret_cast<float2*>(out + (eb + 16) * 128 + c) =
                    make_float2(fmaxf(c1[nf*4+0] + bb.x, 0.f), fmaxf(c1[nf*4+1] + bb.y, 0.f));
                *reinterpret_cast<float2*>(out + (eb + 24) * 128 + c) =
                    make_float2(fmaxf(c1[nf*4+2] + bb.x, 0.f), fmaxf(c1[nf*4+3] + bb.y, 0.f));
            }
        }
    }
}

// ================= host =================
extern "C" void kernel_launch(void* const* d_in, const int* in_sizes, int n_in,
                              void* d_out, int out_size)
{
    const float* V   = (const float*)d_in[0];
    const float* E   = (const float*)d_in[1];
    const int*   src = (const int*)d_in[2];
    const int*   dst = (const int*)d_in[3];
    const float* U_w = (const float*)d_in[4];
    const float* V_w = (const float*)d_in[5];
    const float* P_w = (const float*)d_in[6];
    const float* P_b = (const float*)d_in[7];
    const float* W1  = (const float*)d_in[8];
    const float* b1  = (const float*)d_in[9];
    const float* W2  = (const float*)d_in[10];
    const float* b2  = (const float*)d_in[11];
    float* out = (float*)d_out;

    int n_nodes = in_sizes[0] / 128;
    int n_edges = in_sizes[2];
    int n_tiles = n_edges / 256;                 // 2500
    int n_ntiles = (n_nodes + 255) / 256;        // 391

    static int sms = 0;
    if (!sms) {
        cudaDeviceGetAttribute(&sms, cudaDevAttrMultiProcessorCount, 0);
        cudaFuncSetAttribute(ecat_node, cudaFuncAttributeMaxDynamicSharedMemorySize, NODE_SMEM);
        cudaFuncSetAttribute(ecat_edge, cudaFuncAttributeMaxDynamicSharedMemorySize, EDGE_SMEM);
    }

    ecat_compose<<<128, 128>>>(W1, P_w, P_b, b1);
    ecat_convert<<<4, PTH>>>(W1, W2, U_w, V_w);
    ecat_node<<<sms, NTH, NODE_SMEM>>>(V, n_nodes, n_ntiles);
    ecat_edge<<<sms, ETH, EDGE_SMEM>>>(E, src, dst, b2, out, n_tiles);
}

// round 14
// speedup vs baseline: 2.3949x; 2.0493x over previous
#include <cuda_runtime.h>
#include <cuda_bf16.h>
#include <cuda_fp16.h>
#include <cstdint>

#define NTH   512                        // edge + node: 16 warps, m=16 per warp
#define PTH   512
#define ST    136                        // elems per weight-tile row (272 B bf16 / fp16)
#define TILEB (128 * ST * 2)             // 34816 B per 128x128 16-bit tile
#define EDGE_SMEM (3 * TILEB)            // W1a' W1b W2 fp16 = 104448
#define NODE_SMEM (4 * TILEB)            // U(h,l) V(h,l) bf16 = 139264
#define NODE_PAD 100096

// ---------------- device scratch (static, allowed) ----------------
__device__ __align__(16) float gVU[(size_t)NODE_PAD * 128];
__device__ __align__(16) float gVV[(size_t)NODE_PAD * 128];
__device__ __align__(16) float gB1p[128];
__device__ __align__(16) char  gWf16[3][TILEB];     // fp16 images: W1a', W1b, W2
__device__ __align__(16) char  gWbf[2][2][TILEB];   // bf16 hi/lo: U_w, V_w (node)

// ---------------- PTX helpers ----------------
__device__ __forceinline__ uint32_t smem_u32(const void* p) {
    uint32_t a;
    asm("{ .reg .u64 t; cvta.to.shared.u64 t, %1; cvt.u32.u64 %0, t; }" : "=r"(a) : "l"(p));
    return a;
}
#define LDSM4(r, addr)                                                              \
    asm volatile("ldmatrix.sync.aligned.m8n8.x4.shared.b16 {%0,%1,%2,%3}, [%4];"    \
                 : "=r"((r)[0]), "=r"((r)[1]), "=r"((r)[2]), "=r"((r)[3])           \
                 : "r"(addr))
__device__ __forceinline__ void mma_bf16(float* c, const uint32_t* a, uint32_t b0, uint32_t b1) {
    asm volatile("mma.sync.aligned.m16n8k16.row.col.f32.bf16.bf16.f32 "
                 "{%0,%1,%2,%3}, {%4,%5,%6,%7}, {%8,%9}, {%0,%1,%2,%3};"
                 : "+f"(c[0]), "+f"(c[1]), "+f"(c[2]), "+f"(c[3])
                 : "r"(a[0]), "r"(a[1]), "r"(a[2]), "r"(a[3]), "r"(b0), "r"(b1));
}
__device__ __forceinline__ void mma_f16(float* c, const uint32_t* a, uint32_t b0, uint32_t b1) {
    asm volatile("mma.sync.aligned.m16n8k16.row.col.f32.f16.f16.f32 "
                 "{%0,%1,%2,%3}, {%4,%5,%6,%7}, {%8,%9}, {%0,%1,%2,%3};"
                 : "+f"(c[0]), "+f"(c[1]), "+f"(c[2]), "+f"(c[3])
                 : "r"(a[0]), "r"(a[1]), "r"(a[2]), "r"(a[3]), "r"(b0), "r"(b1));
}
#define CP16(dst, src) \
    asm volatile("cp.async.ca.shared.global [%0], [%1], 16;" :: "r"(dst), "l"(src))
#define CP_COMMIT() asm volatile("cp.async.commit_group;" ::: "memory")
#define CP_WAIT()   asm volatile("cp.async.wait_group 0;" ::: "memory")

// ---------------- numeric helpers ----------------
__device__ __forceinline__ float bf16hi_rn(float a, uint32_t& hbits) {
    uint32_t u = __float_as_uint(a);
    uint32_t r = (u + 0x7FFFu + ((u >> 16) & 1u)) & 0xFFFF0000u;
    hbits = r;
    return __uint_as_float(r);
}
__device__ __forceinline__ uint32_t bf16x2_of(float lo, float hi) {
    uint32_t r;
    asm("cvt.rn.bf16x2.f32 %0, %1, %2;" : "=r"(r) : "f"(hi), "f"(lo));
    return r;
}
__device__ __forceinline__ uint32_t h2_of(float lo, float hi) {
    uint32_t r;
    asm("cvt.rn.f16x2.f32 %0, %1, %2;" : "=r"(r) : "f"(hi), "f"(lo));
    return r;
}
__device__ __forceinline__ void split2(float x, float y, uint32_t& h, uint32_t& l) {
    uint32_t rx, ry;
    float hx = bf16hi_rn(x, rx), hy = bf16hi_rn(y, ry);
    h = __byte_perm(rx, ry, 0x7632);
    l = bf16x2_of(x - hx, y - hy);
}
__device__ __forceinline__ float fast_tanh(float x) {
    float e = __expf(2.f * x);
    return 1.f - __fdividef(2.f, e + 1.f);
}
__device__ __forceinline__ float lk(float v) { return v > 0.f ? v : 0.01f * v; }

// bf16 hi/lo staging (node weights)
__device__ __forceinline__ void stage32(const float* __restrict__ src,
                                        char* Xh, char* Xl, uint32_t off) {
    #pragma unroll
    for (int i = 0; i < 8; ++i) {
        float4 t = reinterpret_cast<const float4*>(src)[i];
        uint32_t r0, r1, r2, r3;
        float h0 = bf16hi_rn(t.x, r0), h1 = bf16hi_rn(t.y, r1);
        float h2 = bf16hi_rn(t.z, r2), h3 = bf16hi_rn(t.w, r3);
        uint2 hh = make_uint2(__byte_perm(r0, r1, 0x7632), __byte_perm(r2, r3, 0x7632));
        uint2 ll = make_uint2(bf16x2_of(t.x - h0, t.y - h1), bf16x2_of(t.z - h2, t.w - h3));
        *reinterpret_cast<uint2*>(Xh + off + i * 8) = hh;
        *reinterpret_cast<uint2*>(Xl + off + i * 8) = ll;
    }
}
// fp16 single staging (edge weights)
__device__ __forceinline__ void stage32h(const float* __restrict__ src,
                                         char* X, uint32_t off) {
    #pragma unroll
    for (int i = 0; i < 8; ++i) {
        float4 t = reinterpret_cast<const float4*>(src)[i];
        uint2 v = make_uint2(h2_of(t.x, t.y), h2_of(t.z, t.w));
        *reinterpret_cast<uint2*>(X + off + i * 8) = v;
    }
}

// bf16 3-term helper for node kernel
__device__ __forceinline__ void mma6(float* acc, const uint32_t* ah, const uint32_t* al,
                                     const uint32_t* bh, const uint32_t* bl) {
    mma_bf16(acc,     ah, bh[0], bh[1]);
    mma_bf16(acc + 4, ah, bh[2], bh[3]);
    mma_bf16(acc,     ah, bl[0], bl[1]);
    mma_bf16(acc + 4, ah, bl[2], bl[3]);
    mma_bf16(acc,     al, bh[0], bh[1]);
    mma_bf16(acc + 4, al, bh[2], bh[3]);
}
__device__ __forceinline__ void gemm_groups(float* acc, const uint32_t* ah, const uint32_t* al,
                                            uint32_t baseH, uint32_t baseL, int ngroups)
{
    #pragma unroll
    for (int g = 0; g < 8; ++g) {
        if (g >= ngroups) break;
        uint32_t bh[4], bl[4];
        LDSM4(bh, baseH + g * (16 * ST * 2));
        LDSM4(bl, baseL + g * (16 * ST * 2));
        mma6(acc + 8 * g, ah, al, bh, bl);
    }
}

// ================= prep 1: W1a' = W1a @ P_w (emit fp16 image 0), b1' =================
__global__ void __launch_bounds__(128, 1)
ecat_compose(const float* __restrict__ W1, const float* __restrict__ P_w,
             const float* __restrict__ P_b, const float* __restrict__ b1)
{
    __shared__ float srow[128];
    int o = blockIdx.x;
    int j = threadIdx.x;
    srow[j] = W1[o * 256 + j];
    __syncthreads();
    float acc = 0.f;
    #pragma unroll 4
    for (int i = 0; i < 128; ++i)
        acc += srow[i] * P_w[i * 128 + j];
    reinterpret_cast<__half*>(gWf16[0])[o * ST + j] = __float2half_rn(acc);
    if (j == 0) {
        float s = 0.f;
        for (int i = 0; i < 128; ++i) s += srow[i] * P_b[i];
        gB1p[o] = b1[o] + s;
    }
}

// ================= prep 2: W1b, W2 -> fp16; U_w, V_w -> bf16 hi/lo =================
__global__ void __launch_bounds__(PTH, 1)
ecat_convert(const float* __restrict__ W1, const float* __restrict__ W2,
             const float* __restrict__ U_w, const float* __restrict__ V_w)
{
    int b = blockIdx.x;
    int tid = threadIdx.x;
    int o = tid >> 2, qo = (tid & 3) * 32;
    uint32_t off = (uint32_t)(o * ST + qo) * 2;
    if (b == 0)      stage32h(W1 + o * 256 + 128 + qo, (char*)gWf16[1], off);
    else if (b == 1) stage32h(W2 + o * 128 + qo, (char*)gWf16[2], off);
    else if (b == 2) stage32(U_w + (size_t)o * 128 + qo, (char*)gWbf[0][0], (char*)gWbf[0][1], off);
    else             stage32(V_w + (size_t)o * 128 + qo, (char*)gWbf[1][0], (char*)gWbf[1][1], off);
}

// ================= prep 3: VU = V@U_w^T, VV = V@V_w^T (persistent, bf16 3-term) =================
__global__ void __launch_bounds__(NTH, 1)
ecat_node(const float* __restrict__ V, int n_nodes, int n_ntiles)
{
    extern __shared__ char sm[];
    uint32_t smb = smem_u32(sm);
    const char* gsrc = &gWbf[0][0][0];
    #pragma unroll
    for (int i = 0; i < 17; ++i) {
        int idx = i * NTH + threadIdx.x;
        CP16(smb + idx * 16, gsrc + idx * 16);   // 17*512 = 8704 chunks exactly
    }
    CP_COMMIT(); CP_WAIT();
    __syncthreads();

    const int tid = threadIdx.x, lane = tid & 31, w = tid >> 5;
    const int r0 = lane >> 2, il = lane & 3, cb = il * 2;
    const uint32_t offB = (uint32_t)(((lane & 7) + (((lane >> 4) & 1) << 3)) * ST
                                     + (((lane >> 3) & 1) << 3)) * 2;

    for (int t = blockIdx.x; t < n_ntiles; t += gridDim.x) {
        int n0 = t * 256 + w * 16 + r0;
        int n1 = n0 + 8;
        int n0c = n0 < n_nodes ? n0 : 0;
        int n1c = n1 < n_nodes ? n1 : 0;
        const float2* pa0 = reinterpret_cast<const float2*>(V + (size_t)n0c * 128);
        const float2* pa1 = reinterpret_cast<const float2*>(V + (size_t)n1c * 128);

        #pragma unroll 1
        for (int pass = 0; pass < 2; ++pass) {
            uint32_t bH = smb + pass * 2 * TILEB, bL = bH + TILEB;
            float acc[64];
            #pragma unroll
            for (int i = 0; i < 64; ++i) acc[i] = 0.f;
            #pragma unroll 1
            for (int ks = 0; ks < 8; ++ks) {
                int i0 = il + 8 * ks, i1 = i0 + 4;
                float2 a0 = pa0[i0], b0 = pa1[i0], c0 = pa0[i1], d0 = pa1[i1];
                uint32_t ah[4], al[4];
                split2(a0.x, a0.y, ah[0], al[0]);
                split2(b0.x, b0.y, ah[1], al[1]);
                split2(c0.x, c0.y, ah[2], al[2]);
                split2(d0.x, d0.y, ah[3], al[3]);
                gemm_groups(acc, ah, al, bH + offB + ks * 32, bL + offB + ks * 32, 8);
            }
            float* dstb = pass ? gVV : gVU;
            #pragma unroll
            for (int nf = 0; nf < 16; ++nf) {
                int c = nf * 8 + cb;
                if (n0 < n_nodes)
                    *reinterpret_cast<float2*>(dstb + (size_t)n0 * 128 + c) =
                        make_float2(acc[nf*4], acc[nf*4+1]);
                if (n1 < n_nodes)
                    *reinterpret_cast<float2*>(dstb + (size_t)n1 * 128 + c) =
                        make_float2(acc[nf*4+2], acc[nf*4+3]);
            }
        }
    }
}

// ================= main edge kernel: fp16 single-term, 16 warps, m=16 =================
__global__ void __launch_bounds__(NTH, 1)
ecat_edge(const float* __restrict__ E, const int* __restrict__ src,
          const int* __restrict__ dst, const float* __restrict__ b2,
          float* __restrict__ out, int n_tiles)
{
    extern __shared__ char sm[];
    uint32_t smb = smem_u32(sm);
    const char* gsrc = &gWf16[0][0];
    #pragma unroll
    for (int i = 0; i < 13; ++i) {                 // 3*TILEB/16 = 6528 chunks
        int idx = i * NTH + threadIdx.x;
        if (idx < 3 * TILEB / 16) CP16(smb + idx * 16, gsrc + idx * 16);
    }
    CP_COMMIT(); CP_WAIT();
    __syncthreads();

    const int tid = threadIdx.x, lane = tid & 31, w = tid >> 5;
    const int r0 = lane >> 2, il = lane & 3, cb = il * 2;
    const uint32_t offB = (uint32_t)(((lane & 7) + (((lane >> 4) & 1) << 3)) * ST
                                     + (((lane >> 3) & 1) << 3)) * 2;
    const uint32_t uW1a = smb;
    const uint32_t uW1b = smb + TILEB;
    const uint32_t uW2  = smb + 2 * TILEB;

    for (int t = blockIdx.x; t < n_tiles; t += gridDim.x) {
        long er0 = (long)t * 256 + w * 16 + r0;
        long er1 = er0 + 8;
        int s0 = __ldg(src + er0), s1 = __ldg(src + er1);
        int d0 = __ldg(dst + er0), d1 = __ldg(dst + er1);
        const float2* pu0 = reinterpret_cast<const float2*>(gVU + (size_t)s0 * 128);
        const float2* pu1 = reinterpret_cast<const float2*>(gVU + (size_t)s1 * 128);
        const float2* pv0 = reinterpret_cast<const float2*>(gVV + (size_t)d0 * 128);
        const float2* pv1 = reinterpret_cast<const float2*>(gVV + (size_t)d1 * 128);
        const float2* pe0 = reinterpret_cast<const float2*>(E + er0 * 128);
        const float2* pe1 = reinterpret_cast<const float2*>(E + er1 * 128);

        float acc[64];
        #pragma unroll
        for (int i = 0; i < 64; ++i) acc[i] = 0.f;

        // ---- merged GEMM A+B, single-term fp16 ----
        #pragma unroll 1
        for (int ks = 0; ks < 8; ++ks) {
            int i0 = il + 8 * ks, i1 = i0 + 4;
            uint32_t th[4], eh[4];
            {
                float2 u0 = pu0[i0], u1 = pu1[i0], u2 = pu0[i1], u3 = pu1[i1];
                float2 v0 = pv0[i0], v1 = pv1[i0], v2 = pv0[i1], v3 = pv1[i1];
                th[0] = h2_of(fast_tanh(u0.x * v0.x), fast_tanh(u0.y * v0.y));
                th[1] = h2_of(fast_tanh(u1.x * v1.x), fast_tanh(u1.y * v1.y));
                th[2] = h2_of(fast_tanh(u2.x * v2.x), fast_tanh(u2.y * v2.y));
                th[3] = h2_of(fast_tanh(u3.x * v3.x), fast_tanh(u3.y * v3.y));
            }
            {
                float2 e0 = pe0[i0], e1 = pe1[i0], e2 = pe0[i1], e3 = pe1[i1];
                eh[0] = h2_of(lk(e0.x), lk(e0.y));
                eh[1] = h2_of(lk(e1.x), lk(e1.y));
                eh[2] = h2_of(lk(e2.x), lk(e2.y));
                eh[3] = h2_of(lk(e3.x), lk(e3.y));
            }
            const uint32_t bA = uW1a + offB + ks * 32;
            const uint32_t bB = uW1b + offB + ks * 32;
            #pragma unroll
            for (int g = 0; g < 8; ++g) {
                uint32_t go = (uint32_t)g * (16 * ST * 2);
                uint32_t ba[4], bb[4];
                LDSM4(ba, bA + go);
                LDSM4(bb, bB + go);
                mma_f16(acc + 8 * g,     th, ba[0], ba[1]);
                mma_f16(acc + 8 * g + 4, th, ba[2], ba[3]);
                mma_f16(acc + 8 * g,     eh, bb[0], bb[1]);
                mma_f16(acc + 8 * g + 4, eh, bb[2], bb[3]);
            }
        }

        // ---- y1 = relu(acc + b1'): repack into fp16 A-frags for GEMM C ----
        uint32_t yv[8][4];
        #pragma unroll
        for (int ks = 0; ks < 8; ++ks) {
            #pragma unroll
            for (int p = 0; p < 2; ++p) {
                int nf = 2 * ks + p;
                float2 bb = __ldg(reinterpret_cast<const float2*>(gB1p + nf * 8 + cb));
                yv[ks][2*p]   = h2_of(fmaxf(acc[nf*4+0] + bb.x, 0.f),
                                      fmaxf(acc[nf*4+1] + bb.y, 0.f));
                yv[ks][2*p+1] = h2_of(fmaxf(acc[nf*4+2] + bb.x, 0.f),
                                      fmaxf(acc[nf*4+3] + bb.y, 0.f));
            }
        }

        // ---- GEMM C: out = relu(y1 @ W2^T + b2), full n in one pass ----
        float acc2[64];
        #pragma unroll
        for (int i = 0; i < 64; ++i) acc2[i] = 0.f;
        #pragma unroll 1
        for (int ks = 0; ks < 8; ++ks) {
            const uint32_t bC = uW2 + offB + ks * 32;
            #pragma unroll
            for (int g = 0; g < 8; ++g) {
                uint32_t go = (uint32_t)g * (16 * ST * 2);
                uint32_t bc[4];
                LDSM4(bc, bC + go);
                mma_f16(acc2 + 8 * g,     yv[ks], bc[0], bc[1]);
                mma_f16(acc2 + 8 * g + 4, yv[ks], bc[2], bc[3]);
            }
        }
        #pragma unroll
        for (int nf = 0; nf < 16; ++nf) {
            int c = nf * 8 + cb;
            float2 bb = __ldg(reinterpret_cast<const float2*>(b2 + c));
            *reinterpret_cast<float2*>(out + er0 * 128 + c) =
                make_float2(fmaxf(acc2[nf*4+0] + bb.x, 0.f),
                            fmaxf(acc2[nf*4+1] + bb.y, 0.f));
            *reinterpret_cast<float2*>(out + er1 * 128 + c) =
                make_float2(fmaxf(acc2[nf*4+2] + bb.x, 0.f),
                            fmaxf(acc2[nf*4+3] + bb.y, 0.f));
        }
    }
}

// ================= host =================
extern "C" void kernel_launch(void* const* d_in, const int* in_sizes, int n_in,
                              void* d_out, int out_size)
{
    const float* V   = (const float*)d_in[0];
    const float* E   = (const float*)d_in[1];
    const int*   src = (const int*)d_in[2];
    const int*   dst = (const int*)d_in[3];
    const float* U_w = (const float*)d_in[4];
    const float* V_w = (const float*)d_in[5];
    const float* P_w = (const float*)d_in[6];
    const float* P_b = (const float*)d_in[7];
    const float* W1  = (const float*)d_in[8];
    const float* b1  = (const float*)d_in[9];
    const float* W2  = (const float*)d_in[10];
    const float* b2  = (const float*)d_in[11];
    float* out = (float*)d_out;

    int n_nodes = in_sizes[0] / 128;
    int n_edges = in_sizes[2];
    int n_tiles = n_edges / 256;                 // 2500
    int n_ntiles = (n_nodes + 255) / 256;        // 391

    static int sms = 0;
    if (!sms) {
        cudaDeviceGetAttribute(&sms, cudaDevAttrMultiProcessorCount, 0);
        cudaFuncSetAttribute(ecat_node, cudaFuncAttributeMaxDynamicSharedMemorySize, NODE_SMEM);
        cudaFuncSetAttribute(ecat_edge, cudaFuncAttributeMaxDynamicSharedMemorySize, EDGE_SMEM);
    }

    ecat_compose<<<128, 128>>>(W1, P_w, P_b, b1);
    ecat_convert<<<4, PTH>>>(W1, W2, U_w, V_w);
    ecat_node<<<sms, NTH, NODE_SMEM>>>(V, n_nodes, n_ntiles);
    ecat_edge<<<sms, NTH, EDGE_SMEM>>>(E, src, dst, b2, out, n_tiles);
}